// round 4
// baseline (speedup 1.0000x reference)
#include <cuda_runtime.h>
#include <math.h>

#define NN 256
#define HH 256
#define DDE 64
#define NHD 4
#define CHUNK 32
#define NCHUNK 8
#define GH_STRIDE 260

typedef unsigned long long ull;

__device__ __forceinline__ ull pk2(float lo, float hi) {
    ull r; asm("mov.b64 %0,{%1,%2};" : "=l"(r) : "f"(lo), "f"(hi)); return r;
}
__device__ __forceinline__ float2 upk2(ull v) {
    float lo, hi; asm("mov.b64 {%0,%1},%2;" : "=f"(lo), "=f"(hi) : "l"(v));
    float2 f; f.x = lo; f.y = hi; return f;
}
__device__ __forceinline__ ull fma2_(ull a, ull b, ull c) {
    ull d; asm("fma.rn.f32x2 %0,%1,%2,%3;" : "=l"(d) : "l"(a), "l"(b), "l"(c)); return d;
}
__device__ __forceinline__ ull mul2_(ull a, ull b) {
    ull d; asm("mul.rn.f32x2 %0,%1,%2;" : "=l"(d) : "l"(a), "l"(b)); return d;
}

// ---------------- device scratch ----------------
__device__ float g_tTj[NN * HH];   // tanh(ahs[j,h])
__device__ float g_PT[DDE * NN];
__device__ float g_C [NN * DDE];
__device__ float g_u [NHD * HH];
__device__ float g_v [NHD * HH];
__device__ float g_msm[NN * NHD * HH];

// ---------------- prep kernels ----------------
__global__ void prepA(const float* __restrict__ ahs, const float* __restrict__ goal,
                      const float* __restrict__ action, const float* __restrict__ Wd,
                      const float* __restrict__ bd) {
    const int j = blockIdx.x, t = threadIdx.x;
    g_tTj[j * HH + t] = tanhf(ahs[j * HH + t]);
    if (t < DDE) {
        const float a0 = action[j * 2 + 0], a1 = action[j * 2 + 1];
        const float go0 = goal[j * 2 + 0], go1 = goal[j * 2 + 1];
        g_PT[t * NN + j] = a0 * Wd[4 * DDE + t] + a1 * Wd[5 * DDE + t]
                         + go0 * Wd[6 * DDE + t] + go1 * Wd[7 * DDE + t];
        g_C[j * DDE + t] = a0 * Wd[0 * DDE + t] + a1 * Wd[1 * DDE + t]
                         + go0 * Wd[2 * DDE + t] + go1 * Wd[3 * DDE + t] + bd[t];
    }
}

__global__ void prepB(const float* __restrict__ w, const float* __restrict__ a) {
    const int warp = (blockIdx.x * blockDim.x + threadIdx.x) >> 5;  // z*256+h
    const int lane = threadIdx.x & 31;
    const float* row = w + warp * HH;
    float su = 0.f, sv = 0.f;
    #pragma unroll
    for (int f = lane; f < HH; f += 32) {
        const float wv = row[f];
        su = fmaf(wv, a[f], su);
        sv = fmaf(wv, a[HH + f], sv);
    }
    #pragma unroll
    for (int o = 16; o; o >>= 1) {
        su += __shfl_down_sync(0xffffffffu, su, o);
        sv += __shfl_down_sync(0xffffffffu, sv, o);
    }
    if (lane == 0) { g_u[warp] = su; g_v[warp] = sv; }
}

// ---------------- main fused kernel ----------------
// smem floats: Wg_s 16384 | qs 2048 | gh 32*260=8320 | spp 256 | psh 128 | bc 16 | cvec 16
#define SM_FLOATS (16384 + 2048 + CHUNK * GH_STRIDE + 256 + 128 + 16 + 16)
#define SM_BYTES  (SM_FLOATS * 4)

__global__ void __launch_bounds__(256, 2) mainK(
    const float* __restrict__ ahs, const float* __restrict__ ghs,
    const float* __restrict__ Wg, const float* __restrict__ bg)
{
    extern __shared__ float sm[];
    float* Wg_s = sm;                       // [d][h]        16384
    float* qs   = Wg_s + DDE * HH;          // [d][jl]       2048
    float* gh   = qs + DDE * CHUNK;         // [jl][h] s=260 8320
    float* spp  = gh + CHUNK * GH_STRIDE;   // [whalf][z][j] 256
    float* psh  = spp + 256;                // [jl][z]       128
    float* bc   = psh + 128;                // 16
    float* cvec = bc + 16;                  // c1[0..3], s0[4..7]

    const int i    = blockIdx.x;
    const int tid  = threadIdx.x;
    const int lane = tid & 31;
    const int warp = tid >> 5;
    const int jg   = tid >> 6;     // 0..3, owns j = jg*8 .. +7
    const int hg   = tid & 63;     // owns h = hg*4 .. +3
    const int wh   = warp & 1;     // h-half of warp

    for (int k = tid; k < DDE * HH; k += 256) Wg_s[k] = Wg[k];

    // prologue dots: warp (z*2+sel): c1/s0 for this row
    if (warp < 8) {
        const int z = warp >> 1;
        const float* src = (warp & 1) ? (g_v + z * HH) : (g_u + z * HH);
        float s = 0.f;
        #pragma unroll
        for (int h = lane; h < HH; h += 32) s = fmaf(ahs[i * HH + h], src[h], s);
        #pragma unroll
        for (int o = 16; o; o >>= 1) s += __shfl_xor_sync(0xffffffffu, s, o);
        if (lane == 0) cvec[(warp & 1) * 4 + z] = s;
    }

    // per-thread v values for the 4 heads at this thread's 4 h
    float vz0[4], vz1[4], vz2[4], vz3[4];
    {
        const float4 a0 = *(const float4*)&g_v[0 * HH + hg * 4];
        const float4 a1 = *(const float4*)&g_v[1 * HH + hg * 4];
        const float4 a2 = *(const float4*)&g_v[2 * HH + hg * 4];
        const float4 a3 = *(const float4*)&g_v[3 * HH + hg * 4];
        vz0[0]=a0.x; vz0[1]=a0.y; vz0[2]=a0.z; vz0[3]=a0.w;
        vz1[0]=a1.x; vz1[1]=a1.y; vz1[2]=a1.z; vz1[3]=a1.w;
        vz2[0]=a2.x; vz2[1]=a2.y; vz2[2]=a2.z; vz2[3]=a2.w;
        vz3[0]=a3.x; vz3[1]=a3.y; vz3[2]=a3.z; vz3[3]=a3.w;
    }
    // gate bias, duplicated for j-paired FFMA2
    ull bgd0, bgd1, bgd2, bgd3;
    {
        const float4 b4 = *(const float4*)&bg[hg * 4];
        bgd0 = pk2(b4.x, b4.x); bgd1 = pk2(b4.y, b4.y);
        bgd2 = pk2(b4.z, b4.z); bgd3 = pk2(b4.w, b4.w);
    }

    const float ahs_i = ahs[i * HH + tid];
    __syncthreads();

    // online-softmax state (replicated across threads)
    float runmax0, runmax1, runmax2, runmax3;
    float denom0 = 1.f, denom1 = 1.f, denom2 = 1.f, denom3 = 1.f;
    {
        const float s0v = cvec[0] + cvec[4], s1v = cvec[1] + cvec[5];
        const float s2v = cvec[2] + cvec[6], s3v = cvec[3] + cvec[7];
        runmax0 = (s0v > 0.f) ? s0v : 0.2f * s0v;
        runmax1 = (s1v > 0.f) ? s1v : 0.2f * s1v;
        runmax2 = (s2v > 0.f) ? s2v : 0.2f * s2v;
        runmax3 = (s3v > 0.f) ? s3v : 0.2f * s3v;
    }
    ull mA = pk2(ahs_i, ahs_i), mB = mA;   // (m0,m1),(m2,m3)

    for (int c = 0; c < NCHUNK; c++) {
        const int j0 = c * CHUNK;

        // qs[d][jj] = relu(C[i,d] + PT[d, j0+jj])
        for (int idx = tid; idx < DDE * CHUNK; idx += 256) {
            const int d = idx >> 5, jj = idx & 31;
            const float val = g_C[i * DDE + d] + g_PT[d * NN + j0 + jj];
            qs[idx] = fmaxf(val, 0.f);
        }
        __syncthreads();

        // ---- gate GEMM: 8 j (4 pairs) x 4 h per thread, f32x2 packed ----
        ull acc[4][4];
        #pragma unroll
        for (int jp = 0; jp < 4; jp++) {
            acc[jp][0] = bgd0; acc[jp][1] = bgd1; acc[jp][2] = bgd2; acc[jp][3] = bgd3;
        }
        #pragma unroll 1
        for (int d = 0; d < DDE; d++) {
            const ulonglong2 qA = *(const ulonglong2*)&qs[d * CHUNK + jg * 8];
            const ulonglong2 qB = *(const ulonglong2*)&qs[d * CHUNK + jg * 8 + 4];
            const float4 wv = *(const float4*)&Wg_s[d * HH + hg * 4];
            const ull w0 = pk2(wv.x, wv.x), w1 = pk2(wv.y, wv.y);
            const ull w2 = pk2(wv.z, wv.z), w3 = pk2(wv.w, wv.w);
            acc[0][0] = fma2_(qA.x, w0, acc[0][0]);
            acc[0][1] = fma2_(qA.x, w1, acc[0][1]);
            acc[0][2] = fma2_(qA.x, w2, acc[0][2]);
            acc[0][3] = fma2_(qA.x, w3, acc[0][3]);
            acc[1][0] = fma2_(qA.y, w0, acc[1][0]);
            acc[1][1] = fma2_(qA.y, w1, acc[1][1]);
            acc[1][2] = fma2_(qA.y, w2, acc[1][2]);
            acc[1][3] = fma2_(qA.y, w3, acc[1][3]);
            acc[2][0] = fma2_(qB.x, w0, acc[2][0]);
            acc[2][1] = fma2_(qB.x, w1, acc[2][1]);
            acc[2][2] = fma2_(qB.x, w2, acc[2][2]);
            acc[2][3] = fma2_(qB.x, w3, acc[2][3]);
            acc[3][0] = fma2_(qB.y, w0, acc[3][0]);
            acc[3][1] = fma2_(qB.y, w1, acc[3][1]);
            acc[3][2] = fma2_(qB.y, w2, acc[3][2]);
            acc[3][3] = fma2_(qB.y, w3, acc[3][3]);
        }

        // ---- epilogue: sigmoid*tanh (diag override), store gh, fused scores ----
        #pragma unroll
        for (int jp = 0; jp < 4; jp++) {
            const float2 x0 = upk2(acc[jp][0]), x1 = upk2(acc[jp][1]);
            const float2 x2 = upk2(acc[jp][2]), x3 = upk2(acc[jp][3]);
            const float xs[2][4] = {{x0.x, x1.x, x2.x, x3.x}, {x0.y, x1.y, x2.y, x3.y}};
            #pragma unroll
            for (int half = 0; half < 2; half++) {
                const int jloc = jg * 8 + jp * 2 + half;
                const int j = j0 + jloc;
                float gv[4];
                if (j == i) {
                    const float4 ga = *(const float4*)&ghs[i * HH + hg * 4];
                    gv[0] = ga.x; gv[1] = ga.y; gv[2] = ga.z; gv[3] = ga.w;
                } else {
                    const float4 ta = *(const float4*)&g_tTj[j * HH + hg * 4];
                    const float t4[4] = {ta.x, ta.y, ta.z, ta.w};
                    #pragma unroll
                    for (int h = 0; h < 4; h++) {
                        const float ex = __expf(-xs[half][h]);
                        gv[h] = __fdividef(1.f, 1.f + ex) * t4[h];
                    }
                }
                *(float4*)&gh[jloc * GH_STRIDE + hg * 4] = make_float4(gv[0], gv[1], gv[2], gv[3]);

                float p0 = 0.f, p1 = 0.f, p2 = 0.f, p3 = 0.f;
                #pragma unroll
                for (int h = 0; h < 4; h++) {
                    p0 = fmaf(gv[h], vz0[h], p0);
                    p1 = fmaf(gv[h], vz1[h], p1);
                    p2 = fmaf(gv[h], vz2[h], p2);
                    p3 = fmaf(gv[h], vz3[h], p3);
                }
                #pragma unroll
                for (int o = 16; o; o >>= 1) {
                    p0 += __shfl_xor_sync(0xffffffffu, p0, o);
                    p1 += __shfl_xor_sync(0xffffffffu, p1, o);
                    p2 += __shfl_xor_sync(0xffffffffu, p2, o);
                    p3 += __shfl_xor_sync(0xffffffffu, p3, o);
                }
                if (lane < 4) {
                    const float sv = (lane == 0) ? p0 : (lane == 1) ? p1 : (lane == 2) ? p2 : p3;
                    spp[wh * 128 + lane * 32 + jloc] = sv;   // raw partial (leaky+c1 later)
                }
            }
        }
        __syncthreads();

        // ---- chunk softmax: warp z in {0..3} ----
        if (warp < 4) {
            const float czv = cvec[warp];
            const float rmz = (warp == 0) ? runmax0 : (warp == 1) ? runmax1
                            : (warp == 2) ? runmax2 : runmax3;
            float e = czv + spp[warp * 32 + lane] + spp[128 + warp * 32 + lane];
            e = (e > 0.f) ? e : 0.2f * e;
            float mx = e;
            #pragma unroll
            for (int o = 16; o; o >>= 1) mx = fmaxf(mx, __shfl_xor_sync(0xffffffffu, mx, o));
            const float nm = fmaxf(rmz, mx);
            const float p = __expf(e - nm);
            psh[lane * 4 + warp] = p;
            float ps = p;
            #pragma unroll
            for (int o = 16; o; o >>= 1) ps += __shfl_xor_sync(0xffffffffu, ps, o);
            if (lane == 0) { bc[warp] = mx; bc[4 + warp] = ps; }
        }
        __syncthreads();

        // ---- merge running state, accumulate m for h = tid ----
        {
            const float nm0 = fmaxf(runmax0, bc[0]);
            const float nm1 = fmaxf(runmax1, bc[1]);
            const float nm2 = fmaxf(runmax2, bc[2]);
            const float nm3 = fmaxf(runmax3, bc[3]);
            const float s0 = __expf(runmax0 - nm0), s1 = __expf(runmax1 - nm1);
            const float s2 = __expf(runmax2 - nm2), s3 = __expf(runmax3 - nm3);
            denom0 = denom0 * s0 + bc[4]; denom1 = denom1 * s1 + bc[5];
            denom2 = denom2 * s2 + bc[6]; denom3 = denom3 * s3 + bc[7];
            runmax0 = nm0; runmax1 = nm1; runmax2 = nm2; runmax3 = nm3;
            mA = mul2_(mA, pk2(s0, s1));
            mB = mul2_(mB, pk2(s2, s3));
        }
        #pragma unroll 4
        for (int jj = 0; jj < CHUNK; jj++) {
            const float ghv = gh[jj * GH_STRIDE + tid];
            const ulonglong2 pp = *(const ulonglong2*)&psh[jj * 4];
            const ull gd = pk2(ghv, ghv);
            mA = fma2_(pp.x, gd, mA);
            mB = fma2_(pp.y, gd, mB);
        }
        __syncthreads();
    }

    // write normalized m: g_msm[i][z*256 + h]
    {
        const float2 fA = upk2(mA), fB = upk2(mB);
        g_msm[i * (NHD * HH) + 0 * HH + tid] = fA.x / denom0;
        g_msm[i * (NHD * HH) + 1 * HH + tid] = fA.y / denom1;
        g_msm[i * (NHD * HH) + 2 * HH + tid] = fB.x / denom2;
        g_msm[i * (NHD * HH) + 3 * HH + tid] = fB.y / denom3;
    }
}

// ---------------- projection kernel ----------------
__global__ void __launch_bounds__(256) projK(const float* __restrict__ w,
                                             const float* __restrict__ bias,
                                             float* __restrict__ out) {
    __shared__ float msm_s[8192];   // [k][n]
    __shared__ float sacc[2048];
    const int tid = threadIdx.x;
    const int f0 = (blockIdx.x & 7) * 32;
    const int n0 = (blockIdx.x >> 3) * 8;

    for (int idx = tid; idx < 8192; idx += 256) {
        const int k = idx >> 3, n = idx & 7;
        msm_s[idx] = g_msm[(n0 + n) * 1024 + k];
    }
    __syncthreads();

    const int fl = tid & 31, kw = tid >> 5;
    ull accA[4];
    #pragma unroll
    for (int n = 0; n < 4; n++) accA[n] = 0ull;
    const float* wp = w + f0 + fl;
    const int kbeg = kw * 128;
    #pragma unroll 4
    for (int k = kbeg; k < kbeg + 128; k++) {
        const float wv = wp[k * 256];
        const ull wd = pk2(wv, wv);
        const ulonglong2 m0 = *(const ulonglong2*)&msm_s[k * 8];
        const ulonglong2 m1 = *(const ulonglong2*)&msm_s[k * 8 + 4];
        accA[0] = fma2_(wd, m0.x, accA[0]);
        accA[1] = fma2_(wd, m0.y, accA[1]);
        accA[2] = fma2_(wd, m1.x, accA[2]);
        accA[3] = fma2_(wd, m1.y, accA[3]);
    }
    #pragma unroll
    for (int np = 0; np < 4; np++) {
        const float2 f = upk2(accA[np]);
        sacc[(kw * 8 + np * 2 + 0) * 32 + fl] = f.x;
        sacc[(kw * 8 + np * 2 + 1) * 32 + fl] = f.y;
    }
    __syncthreads();

    const int n = tid >> 5;
    float s = 0.f;
    #pragma unroll
    for (int k2 = 0; k2 < 8; k2++) s += sacc[(k2 * 8 + n) * 32 + fl];
    out[(n0 + n) * 256 + f0 + fl] = fmaxf(0.25f * s, 0.f) + bias[f0 + fl];
}

// ---------------- launch ----------------
extern "C" void kernel_launch(void* const* d_in, const int* in_sizes, int n_in,
                              void* d_out, int out_size) {
    (void)in_sizes; (void)n_in; (void)out_size;
    const float* ahs    = (const float*)d_in[0];
    const float* ghs    = (const float*)d_in[1];
    const float* goal   = (const float*)d_in[2];
    const float* action = (const float*)d_in[3];
    const float* Wd     = (const float*)d_in[4];
    const float* bd     = (const float*)d_in[5];
    const float* Wg     = (const float*)d_in[6];
    const float* bg     = (const float*)d_in[7];
    const float* w      = (const float*)d_in[8];
    const float* a      = (const float*)d_in[9];
    const float* bias   = (const float*)d_in[10];
    float* out = (float*)d_out;

    cudaFuncSetAttribute(mainK, cudaFuncAttributeMaxDynamicSharedMemorySize, SM_BYTES);

    prepA<<<NN, 256>>>(ahs, goal, action, Wd, bd);
    prepB<<<128, 256>>>(w, a);
    mainK<<<NN, 256, SM_BYTES>>>(ahs, ghs, Wg, bg);
    projK<<<NN, 256>>>(w, bias, out);
}